// round 12
// baseline (speedup 1.0000x reference)
#include <cuda_runtime.h>

// ---------------------------------------------------------------------------
// CausalEdgeAttention — algebraically reduced, 2-pass recompute.
//   out = edge_attr + 0.5*((relu(ctx@W1+b1) * g) @ M + const8)
//   ctx = 0.5*(nf[src]+nf[tgt]);  M = n_W2@Wv@Wo@Wp (256x8)
// R9 postmortem: single-block merged fold kernel was costing ~150-190us
//   (2304x256 dots on ONE SM, LSU-bound). Split back to kA/kB/kC at
//   18x128 (multi-SM). kStats = proven tiled-ctx (76us). kOut = proven R1.
// ---------------------------------------------------------------------------

#define STATS_BLOCKS 592               // 4 blocks/SM * 148 SMs, one wave
#define TILE 256

__device__ __align__(16) float g_U[256 * 8];
__device__ __align__(16) float g_V[256 * 8];
__device__ __align__(16) float g_M[256 * 8];
__device__ __align__(16) float g_Mg[256 * 8];
__device__ float g_c1[256];
__device__ float g_c2[256];
__device__ float g_c3[8];
__device__ __align__(16) float g_const8[8];
__device__ __align__(16) float g_part[STATS_BLOCKS * 512];

// ---- packed f32x2 helpers -------------------------------------------------
__device__ __forceinline__ unsigned long long pk2(float lo, float hi) {
    unsigned long long r;
    asm("mov.b64 %0, {%1, %2};" : "=l"(r) : "f"(lo), "f"(hi));
    return r;
}
__device__ __forceinline__ void upk2(unsigned long long v, float& lo, float& hi) {
    asm("mov.b64 {%0, %1}, %2;" : "=f"(lo), "=f"(hi) : "l"(v));
}
#define FMA2(d, a, b, c) asm("fma.rn.f32x2 %0, %1, %2, %3;" : "=l"(d) : "l"(a), "l"(b), "l"(c))
#define ADD2(d, a, b)    asm("add.rn.f32x2 %0, %1, %2;" : "=l"(d) : "l"(a), "l"(b))

// ---- folding kernels, 18 blocks x 128 threads (multi-SM, LSU-spread) ------
// U = Wo@Wp ; c1 = nb2@Wv + bv
__global__ void __launch_bounds__(128) kA(
    const float* __restrict__ Wo, const float* __restrict__ Wp,
    const float* __restrict__ nb2, const float* __restrict__ Wv,
    const float* __restrict__ bv) {
    int tid = blockIdx.x * 128 + threadIdx.x;
    if (tid < 2048) {
        int i = tid >> 3, d = tid & 7;
        float a0 = 0.f, a1 = 0.f, a2 = 0.f, a3 = 0.f;
        for (int k = 0; k < 256; k += 4) {
            a0 = fmaf(Wo[i * 256 + k],     Wp[k * 8 + d],       a0);
            a1 = fmaf(Wo[i * 256 + k + 1], Wp[(k + 1) * 8 + d], a1);
            a2 = fmaf(Wo[i * 256 + k + 2], Wp[(k + 2) * 8 + d], a2);
            a3 = fmaf(Wo[i * 256 + k + 3], Wp[(k + 3) * 8 + d], a3);
        }
        g_U[tid] = (a0 + a1) + (a2 + a3);
    } else if (tid < 2304) {
        int i = tid - 2048;
        float a0 = bv[i], a1 = 0.f, a2 = 0.f, a3 = 0.f;
        for (int k = 0; k < 256; k += 4) {
            a0 = fmaf(nb2[k],     Wv[k * 256 + i],       a0);
            a1 = fmaf(nb2[k + 1], Wv[(k + 1) * 256 + i], a1);
            a2 = fmaf(nb2[k + 2], Wv[(k + 2) * 256 + i], a2);
            a3 = fmaf(nb2[k + 3], Wv[(k + 3) * 256 + i], a3);
        }
        g_c1[i] = (a0 + a1) + (a2 + a3);
    }
}

// V = Wv@U ; c2 = c1@Wo + bo
__global__ void __launch_bounds__(128) kB(
    const float* __restrict__ Wv, const float* __restrict__ Wo,
    const float* __restrict__ bo) {
    int tid = blockIdx.x * 128 + threadIdx.x;
    if (tid < 2048) {
        int i = tid >> 3, d = tid & 7;
        float a0 = 0.f, a1 = 0.f, a2 = 0.f, a3 = 0.f;
        for (int k = 0; k < 256; k += 4) {
            a0 = fmaf(Wv[i * 256 + k],     g_U[k * 8 + d],       a0);
            a1 = fmaf(Wv[i * 256 + k + 1], g_U[(k + 1) * 8 + d], a1);
            a2 = fmaf(Wv[i * 256 + k + 2], g_U[(k + 2) * 8 + d], a2);
            a3 = fmaf(Wv[i * 256 + k + 3], g_U[(k + 3) * 8 + d], a3);
        }
        g_V[tid] = (a0 + a1) + (a2 + a3);
    } else if (tid < 2304) {
        int i = tid - 2048;
        float a0 = bo[i], a1 = 0.f, a2 = 0.f, a3 = 0.f;
        for (int k = 0; k < 256; k += 4) {
            a0 = fmaf(g_c1[k],     Wo[k * 256 + i],       a0);
            a1 = fmaf(g_c1[k + 1], Wo[(k + 1) * 256 + i], a1);
            a2 = fmaf(g_c1[k + 2], Wo[(k + 2) * 256 + i], a2);
            a3 = fmaf(g_c1[k + 3], Wo[(k + 3) * 256 + i], a3);
        }
        g_c2[i] = (a0 + a1) + (a2 + a3);
    }
}

// M = nW2@V ; c3 = c2@Wp + bp
__global__ void __launch_bounds__(128) kC(
    const float* __restrict__ nW2, const float* __restrict__ Wp,
    const float* __restrict__ bp) {
    int tid = blockIdx.x * 128 + threadIdx.x;
    if (tid < 2048) {
        int i = tid >> 3, d = tid & 7;
        float a0 = 0.f, a1 = 0.f, a2 = 0.f, a3 = 0.f;
        for (int k = 0; k < 256; k += 4) {
            a0 = fmaf(nW2[i * 256 + k],     g_V[k * 8 + d],       a0);
            a1 = fmaf(nW2[i * 256 + k + 1], g_V[(k + 1) * 8 + d], a1);
            a2 = fmaf(nW2[i * 256 + k + 2], g_V[(k + 2) * 8 + d], a2);
            a3 = fmaf(nW2[i * 256 + k + 3], g_V[(k + 3) * 8 + d], a3);
        }
        g_M[tid] = (a0 + a1) + (a2 + a3);
    } else if (tid < 2056) {
        int d = tid - 2048;
        float acc = bp[d];
        for (int k = 0; k < 256; k++) acc = fmaf(g_c2[k], Wp[k * 8 + d], acc);
        g_c3[d] = acc;
    }
}

// ---- pass 1: tiled-ctx batch stats of h = relu(ctx@W1+b1) -----------------
__global__ void __launch_bounds__(256) kStats(
    const float* __restrict__ nf, const int* __restrict__ ei,
    const float* __restrict__ W1, const float* __restrict__ b1, int E) {
    __shared__ unsigned long long sCtx[2][TILE][4];   // 16KB, (a+b) packed f32x2

    int tid = threadIdx.x;
    int j = tid;                         // owned column

    unsigned long long w01 = pk2(0.5f * W1[0 * 256 + j], 0.5f * W1[1 * 256 + j]);
    unsigned long long w23 = pk2(0.5f * W1[2 * 256 + j], 0.5f * W1[3 * 256 + j]);
    unsigned long long w45 = pk2(0.5f * W1[4 * 256 + j], 0.5f * W1[5 * 256 + j]);
    unsigned long long w67 = pk2(0.5f * W1[6 * 256 + j], 0.5f * W1[7 * 256 + j]);
    unsigned long long b2 = pk2(b1[j], 0.f);

    float s = 0.f, q = 0.f;

    int per = (E + STATS_BLOCKS - 1) / STATS_BLOCKS;
    int start = blockIdx.x * per;
    int len = min(per, E - start);
    int nt = (len + TILE - 1) / TILE;

    const ulonglong4* nfq = (const ulonglong4*)nf;

    {
        int e = start + tid;
        if (tid < len) {
            int a = ei[e], b = ei[E + e];
            ulonglong4 A = nfq[a], B = nfq[b];
            unsigned long long c0, c1, c2, c3;
            ADD2(c0, A.x, B.x); ADD2(c1, A.y, B.y);
            ADD2(c2, A.z, B.z); ADD2(c3, A.w, B.w);
            sCtx[0][tid][0] = c0; sCtx[0][tid][1] = c1;
            sCtx[0][tid][2] = c2; sCtx[0][tid][3] = c3;
        }
    }

    for (int t = 0; t < nt; t++) {
        __syncthreads();

        if (t + 1 < nt) {
            int e = start + (t + 1) * TILE + tid;
            if (e < start + len) {
                int buf = (t + 1) & 1;
                int a = ei[e], b = ei[E + e];
                ulonglong4 A = nfq[a], B = nfq[b];
                unsigned long long c0, c1, c2, c3;
                ADD2(c0, A.x, B.x); ADD2(c1, A.y, B.y);
                ADD2(c2, A.z, B.z); ADD2(c3, A.w, B.w);
                sCtx[buf][tid][0] = c0; sCtx[buf][tid][1] = c1;
                sCtx[buf][tid][2] = c2; sCtx[buf][tid][3] = c3;
            }
        }

        int buf = t & 1;
        int tlen = min(TILE, len - t * TILE);
        const ulonglong2* cb = (const ulonglong2*)&sCtx[buf][0][0];
#pragma unroll 4
        for (int tt = 0; tt < tlen; tt++) {
            ulonglong2 c01 = cb[2 * tt];
            ulonglong2 c23 = cb[2 * tt + 1];
            unsigned long long acc;
            FMA2(acc, c01.x, w01, b2);
            FMA2(acc, c01.y, w23, acc);
            FMA2(acc, c23.x, w45, acc);
            FMA2(acc, c23.y, w67, acc);
            float lo, hi;
            upk2(acc, lo, hi);
            float h = fmaxf(lo + hi, 0.f);
            s += h;
            q = fmaf(h, h, q);
        }
    }

    g_part[blockIdx.x * 512 + tid] = s;
    g_part[blockIdx.x * 512 + 256 + tid] = q;
}

// ---- BN finalize: fold stats into g_Mg / const8 ---------------------------
__global__ void __launch_bounds__(256) kFin(
    const float* __restrict__ gamma, const float* __restrict__ beta,
    float invE) {
    __shared__ float sh[256];
    int j = threadIdx.x;

    float s0 = 0.f, s1 = 0.f, q0 = 0.f, q1 = 0.f;
    for (int b = 0; b < STATS_BLOCKS; b += 2) {
        s0 += g_part[b * 512 + j];
        q0 += g_part[b * 512 + 256 + j];
        s1 += g_part[(b + 1) * 512 + j];
        q1 += g_part[(b + 1) * 512 + 256 + j];
    }
    float s = s0 + s1, q = q0 + q1;
    float mu = s * invE;
    float var = q * invE - mu * mu;
    float gg = gamma[j] * rsqrtf(var + 1e-5f);
    sh[j] = beta[j] - mu * gg;
#pragma unroll
    for (int d = 0; d < 8; d++) g_Mg[j * 8 + d] = gg * g_M[j * 8 + d];
    __syncthreads();

    int w = j >> 5, lane = j & 31;   // warp w -> const8[w]
    float acc = 0.f;
    for (int jj = lane; jj < 256; jj += 32) acc += sh[jj] * g_M[jj * 8 + w];
#pragma unroll
    for (int off = 16; off; off >>= 1)
        acc += __shfl_xor_sync(0xffffffffu, acc, off);
    if (lane == 0) g_const8[w] = acc + g_c3[w];
}

// ---- pass 2: output, thread-per-edge (proven R1 structure) ----------------
__global__ void __launch_bounds__(256) kOut(
    const float* __restrict__ nf, const int* __restrict__ ei,
    const float* __restrict__ W1, const float* __restrict__ b1,
    const float* __restrict__ ea, float* __restrict__ out, int E) {
    __shared__ float4 sW[512];  // W1 transposed: row j = 8 floats
    __shared__ float4 sM[512];  // g-scaled M: row j = 8 floats
    __shared__ float sB[256];
    __shared__ float sC[8];

    int tid = threadIdx.x;
    float* sWf = (float*)sW;
    float* sMf = (float*)sM;
    for (int i = tid; i < 2048; i += 256) {
        int j = i >> 3, d = i & 7;
        sWf[i] = W1[d * 256 + j];
        sMf[i] = g_Mg[i];
    }
    sB[tid] = b1[tid];
    if (tid < 8) sC[tid] = g_const8[tid];
    __syncthreads();

    int e = blockIdx.x * 256 + tid;
    if (e >= E) return;

    int a = ei[e], b = ei[E + e];
    const float4* nf4 = (const float4*)nf;
    float4 a0 = nf4[a * 2], a1 = nf4[a * 2 + 1];
    float4 b0 = nf4[b * 2], b1v = nf4[b * 2 + 1];
    float c[8];
    c[0] = 0.5f * (a0.x + b0.x); c[1] = 0.5f * (a0.y + b0.y);
    c[2] = 0.5f * (a0.z + b0.z); c[3] = 0.5f * (a0.w + b0.w);
    c[4] = 0.5f * (a1.x + b1v.x); c[5] = 0.5f * (a1.y + b1v.y);
    c[6] = 0.5f * (a1.z + b1v.z); c[7] = 0.5f * (a1.w + b1v.w);

    float y[8];
#pragma unroll
    for (int d = 0; d < 8; d++) y[d] = 0.f;

#pragma unroll 8
    for (int j = 0; j < 256; j++) {
        float4 w0 = sW[j * 2], w1 = sW[j * 2 + 1];
        float h = sB[j];
        h += c[0] * w0.x; h += c[1] * w0.y; h += c[2] * w0.z; h += c[3] * w0.w;
        h += c[4] * w1.x; h += c[5] * w1.y; h += c[6] * w1.z; h += c[7] * w1.w;
        h = fmaxf(h, 0.f);
        float4 m0 = sM[j * 2], m1 = sM[j * 2 + 1];
        y[0] += h * m0.x; y[1] += h * m0.y; y[2] += h * m0.z; y[3] += h * m0.w;
        y[4] += h * m1.x; y[5] += h * m1.y; y[6] += h * m1.z; y[7] += h * m1.w;
    }

    const float4* ea4 = (const float4*)ea;
    float4 e0 = ea4[e * 2], e1 = ea4[e * 2 + 1];
    float4 o0, o1;
    o0.x = e0.x + 0.5f * (y[0] + sC[0]);
    o0.y = e0.y + 0.5f * (y[1] + sC[1]);
    o0.z = e0.z + 0.5f * (y[2] + sC[2]);
    o0.w = e0.w + 0.5f * (y[3] + sC[3]);
    o1.x = e1.x + 0.5f * (y[4] + sC[4]);
    o1.y = e1.y + 0.5f * (y[5] + sC[5]);
    o1.z = e1.z + 0.5f * (y[6] + sC[6]);
    o1.w = e1.w + 0.5f * (y[7] + sC[7]);
    float4* out4 = (float4*)out;
    out4[e * 2] = o0;
    out4[e * 2 + 1] = o1;
}

// ---------------------------------------------------------------------------
extern "C" void kernel_launch(void* const* d_in, const int* in_sizes, int n_in,
                              void* d_out, int out_size) {
    const float* edge_attr = (const float*)d_in[0];
    const float* nf        = (const float*)d_in[1];
    const int*   ei        = (const int*)d_in[2];
    // d_in[3..8]: edge-encoder params (dead code in reference)
    const float* nW1   = (const float*)d_in[9];
    const float* nb1   = (const float*)d_in[10];
    const float* ngam  = (const float*)d_in[11];
    const float* nbet  = (const float*)d_in[12];
    const float* nW2   = (const float*)d_in[13];
    const float* nb2   = (const float*)d_in[14];
    const float* Wv    = (const float*)d_in[15];
    const float* bv    = (const float*)d_in[16];
    const float* Wo    = (const float*)d_in[17];
    const float* bo    = (const float*)d_in[18];
    const float* Wp    = (const float*)d_in[19];
    const float* bp    = (const float*)d_in[20];
    float* out = (float*)d_out;

    int E = in_sizes[0] / 8;

    kStats<<<STATS_BLOCKS, 256>>>(nf, ei, nW1, nb1, E);
    kA<<<18, 128>>>(Wo, Wp, nb2, Wv, bv);
    kB<<<18, 128>>>(Wv, Wo, bo);
    kC<<<18, 128>>>(nW2, Wp, bp);
    kFin<<<1, 256>>>(ngam, nbet, 1.0f / (float)E);
    kOut<<<(E + 255) / 256, 256>>>(nf, ei, nW1, nb1, edge_attr, out, E);
}

// round 14
// speedup vs baseline: 1.7267x; 1.7267x over previous
#include <cuda_runtime.h>

// ---------------------------------------------------------------------------
// CausalEdgeAttention — algebraically reduced, SINGLE fused persistent kernel.
//   out = edge_attr + 0.5*((relu(ctx@W1+b1) * g) @ M + const8)
//   ctx = 0.5*(nf[src]+nf[tgt]);  M = n_W2@Wv@Wo@Wp (256x8)
// R12 postmortem: per-kernel models never summed to dur_us — ~100-200us lived
//   in launch boundaries (cold caches / tails on tiny fold kernels). Fuse
//   everything into one 592-block persistent kernel (one wave, 4/SM) with
//   atomic spin barriers; fold runs on 8 blocks concurrently with stats.
// ---------------------------------------------------------------------------

#define NSTATS 584                 // blocks doing stats
#define NFOLD  8                   // blocks doing weight folding
#define NBLK   (NSTATS + NFOLD)    // 592 = 4/SM * 148 SMs, one wave
#define TILE   256

__device__ __align__(16) float g_U[256 * 8];
__device__ __align__(16) float g_V[256 * 8];
__device__ __align__(16) float g_M[256 * 8];
__device__ __align__(16) float g_Mg[256 * 8];
__device__ float g_c1[256];
__device__ float g_c2[256];
__device__ float g_c3[8];
__device__ __align__(16) float g_const8[8];
__device__ __align__(16) float g_part[NSTATS * 512];
__device__ int g_ctrA, g_ctrB, g_ctrC, g_ctrS, g_ctrR;

// ---- packed f32x2 helpers -------------------------------------------------
__device__ __forceinline__ unsigned long long pk2(float lo, float hi) {
    unsigned long long r;
    asm("mov.b64 %0, {%1, %2};" : "=l"(r) : "f"(lo), "f"(hi));
    return r;
}
__device__ __forceinline__ void upk2(unsigned long long v, float& lo, float& hi) {
    asm("mov.b64 {%0, %1}, %2;" : "=f"(lo), "=f"(hi) : "l"(v));
}
#define FMA2(d, a, b, c) asm("fma.rn.f32x2 %0, %1, %2, %3;" : "=l"(d) : "l"(a), "l"(b), "l"(c))
#define ADD2(d, a, b)    asm("add.rn.f32x2 %0, %1, %2;" : "=l"(d) : "l"(a), "l"(b))

// ---- spin barrier helpers -------------------------------------------------
__device__ __forceinline__ void arrive(int* ctr) {
    __syncthreads();
    __threadfence();
    if (threadIdx.x == 0) atomicAdd(ctr, 1);
}
__device__ __forceinline__ void waitFor(int* ctr, int target) {
    if (threadIdx.x == 0) {
        while (atomicAdd(ctr, 0) < target) __nanosleep(128);
        __threadfence();
    }
    __syncthreads();
}

// ---- reset kernel (counters must be zero at each graph replay) ------------
__global__ void kReset() {
    g_ctrA = 0; g_ctrB = 0; g_ctrC = 0; g_ctrS = 0; g_ctrR = 0;
}

// ---- fold stage bodies ----------------------------------------------------
__device__ void foldA(int t, const float* __restrict__ Wo,
                      const float* __restrict__ Wp, const float* __restrict__ nb2,
                      const float* __restrict__ Wv, const float* __restrict__ bv) {
    if (t < 2048) {
        int i = t >> 3, d = t & 7;
        float a0 = 0.f, a1 = 0.f, a2 = 0.f, a3 = 0.f;
        for (int k = 0; k < 256; k += 4) {
            a0 = fmaf(Wo[i * 256 + k],     Wp[k * 8 + d],       a0);
            a1 = fmaf(Wo[i * 256 + k + 1], Wp[(k + 1) * 8 + d], a1);
            a2 = fmaf(Wo[i * 256 + k + 2], Wp[(k + 2) * 8 + d], a2);
            a3 = fmaf(Wo[i * 256 + k + 3], Wp[(k + 3) * 8 + d], a3);
        }
        g_U[t] = (a0 + a1) + (a2 + a3);
    } else if (t < 2304) {
        int i = t - 2048;
        float a0 = bv[i], a1 = 0.f, a2 = 0.f, a3 = 0.f;
        for (int k = 0; k < 256; k += 4) {
            a0 = fmaf(nb2[k],     Wv[k * 256 + i],       a0);
            a1 = fmaf(nb2[k + 1], Wv[(k + 1) * 256 + i], a1);
            a2 = fmaf(nb2[k + 2], Wv[(k + 2) * 256 + i], a2);
            a3 = fmaf(nb2[k + 3], Wv[(k + 3) * 256 + i], a3);
        }
        g_c1[i] = (a0 + a1) + (a2 + a3);
    }
}

__device__ void foldB(int t, const float* __restrict__ Wv,
                      const float* __restrict__ Wo, const float* __restrict__ bo) {
    if (t < 2048) {
        int i = t >> 3, d = t & 7;
        float a0 = 0.f, a1 = 0.f, a2 = 0.f, a3 = 0.f;
        for (int k = 0; k < 256; k += 4) {
            a0 = fmaf(Wv[i * 256 + k],     g_U[k * 8 + d],       a0);
            a1 = fmaf(Wv[i * 256 + k + 1], g_U[(k + 1) * 8 + d], a1);
            a2 = fmaf(Wv[i * 256 + k + 2], g_U[(k + 2) * 8 + d], a2);
            a3 = fmaf(Wv[i * 256 + k + 3], g_U[(k + 3) * 8 + d], a3);
        }
        g_V[t] = (a0 + a1) + (a2 + a3);
    } else if (t < 2304) {
        int i = t - 2048;
        float a0 = bo[i], a1 = 0.f, a2 = 0.f, a3 = 0.f;
        for (int k = 0; k < 256; k += 4) {
            a0 = fmaf(g_c1[k],     Wo[k * 256 + i],       a0);
            a1 = fmaf(g_c1[k + 1], Wo[(k + 1) * 256 + i], a1);
            a2 = fmaf(g_c1[k + 2], Wo[(k + 2) * 256 + i], a2);
            a3 = fmaf(g_c1[k + 3], Wo[(k + 3) * 256 + i], a3);
        }
        g_c2[i] = (a0 + a1) + (a2 + a3);
    }
}

__device__ void foldC(int t, const float* __restrict__ nW2,
                      const float* __restrict__ Wp, const float* __restrict__ bp) {
    if (t < 2048) {
        int i = t >> 3, d = t & 7;
        float a0 = 0.f, a1 = 0.f, a2 = 0.f, a3 = 0.f;
        for (int k = 0; k < 256; k += 4) {
            a0 = fmaf(nW2[i * 256 + k],     g_V[k * 8 + d],       a0);
            a1 = fmaf(nW2[i * 256 + k + 1], g_V[(k + 1) * 8 + d], a1);
            a2 = fmaf(nW2[i * 256 + k + 2], g_V[(k + 2) * 8 + d], a2);
            a3 = fmaf(nW2[i * 256 + k + 3], g_V[(k + 3) * 8 + d], a3);
        }
        g_M[t] = (a0 + a1) + (a2 + a3);
    } else if (t < 2056) {
        int d = t - 2048;
        float acc = bp[d];
        for (int k = 0; k < 256; k++) acc = fmaf(g_c2[k], Wp[k * 8 + d], acc);
        g_c3[d] = acc;
    }
}

// ---- the fused kernel -----------------------------------------------------
__global__ void __launch_bounds__(256, 4) kFused(
    const float* __restrict__ nf, const int* __restrict__ ei,
    const float* __restrict__ W1, const float* __restrict__ b1,
    const float* __restrict__ gamma, const float* __restrict__ beta,
    const float* __restrict__ Wo, const float* __restrict__ Wp,
    const float* __restrict__ nb2, const float* __restrict__ Wv,
    const float* __restrict__ bv, const float* __restrict__ bo,
    const float* __restrict__ nW2, const float* __restrict__ bp,
    const float* __restrict__ ea, float* __restrict__ out,
    int E, float invE) {
    __shared__ unsigned long long sCtx[2][TILE][4];   // 16KB (stats phase)
    __shared__ float4 sW[512];                        // 8KB (out phase)
    __shared__ float4 sM[512];                        // 8KB
    __shared__ float sB[256];
    __shared__ float sC[8];
    __shared__ float sh[256];                         // fin phase (block 0)

    int tid = threadIdx.x;
    int bid = blockIdx.x;
    const ulonglong4* nfq = (const ulonglong4*)nf;

    if (bid < NSTATS) {
        // ---------------- phase 1: BN stats over this block's edge slice ----
        int j = tid;
        unsigned long long w01 = pk2(0.5f * W1[0 * 256 + j], 0.5f * W1[1 * 256 + j]);
        unsigned long long w23 = pk2(0.5f * W1[2 * 256 + j], 0.5f * W1[3 * 256 + j]);
        unsigned long long w45 = pk2(0.5f * W1[4 * 256 + j], 0.5f * W1[5 * 256 + j]);
        unsigned long long w67 = pk2(0.5f * W1[6 * 256 + j], 0.5f * W1[7 * 256 + j]);
        unsigned long long b2 = pk2(b1[j], 0.f);

        float s = 0.f, q = 0.f;
        int per = (E + NSTATS - 1) / NSTATS;
        int start = bid * per;
        int len = min(per, E - start);
        if (len < 0) len = 0;
        int nt = (len + TILE - 1) / TILE;

        if (tid < len) {
            int e = start + tid;
            int a = ei[e], b = ei[E + e];
            ulonglong4 A = nfq[a], B = nfq[b];
            unsigned long long c0, c1, c2, c3;
            ADD2(c0, A.x, B.x); ADD2(c1, A.y, B.y);
            ADD2(c2, A.z, B.z); ADD2(c3, A.w, B.w);
            sCtx[0][tid][0] = c0; sCtx[0][tid][1] = c1;
            sCtx[0][tid][2] = c2; sCtx[0][tid][3] = c3;
        }

        for (int t = 0; t < nt; t++) {
            __syncthreads();
            if (t + 1 < nt) {
                int e = start + (t + 1) * TILE + tid;
                if (e < start + len) {
                    int buf = (t + 1) & 1;
                    int a = ei[e], b = ei[E + e];
                    ulonglong4 A = nfq[a], B = nfq[b];
                    unsigned long long c0, c1, c2, c3;
                    ADD2(c0, A.x, B.x); ADD2(c1, A.y, B.y);
                    ADD2(c2, A.z, B.z); ADD2(c3, A.w, B.w);
                    sCtx[buf][tid][0] = c0; sCtx[buf][tid][1] = c1;
                    sCtx[buf][tid][2] = c2; sCtx[buf][tid][3] = c3;
                }
            }
            int buf = t & 1;
            int tlen = min(TILE, len - t * TILE);
            const ulonglong2* cb = (const ulonglong2*)&sCtx[buf][0][0];
#pragma unroll 4
            for (int tt = 0; tt < tlen; tt++) {
                ulonglong2 c01 = cb[2 * tt];
                ulonglong2 c23 = cb[2 * tt + 1];
                unsigned long long acc;
                FMA2(acc, c01.x, w01, b2);
                FMA2(acc, c01.y, w23, acc);
                FMA2(acc, c23.x, w45, acc);
                FMA2(acc, c23.y, w67, acc);
                float lo, hi;
                upk2(acc, lo, hi);
                float h = fmaxf(lo + hi, 0.f);
                s += h;
                q = fmaf(h, h, q);
            }
        }
        g_part[bid * 512 + tid] = s;
        g_part[bid * 512 + 256 + tid] = q;
        arrive(&g_ctrS);
    } else {
        // ---------------- fold chain on 8 blocks (concurrent with stats) ----
        int t0 = (bid - NSTATS) * 256 + tid;
        foldA(t0, Wo, Wp, nb2, Wv, bv);
        foldA(t0 + 2048, Wo, Wp, nb2, Wv, bv);
        arrive(&g_ctrA);
        waitFor(&g_ctrA, NFOLD);
        foldB(t0, Wv, Wo, bo);
        foldB(t0 + 2048, Wv, Wo, bo);
        arrive(&g_ctrB);
        waitFor(&g_ctrB, NFOLD);
        foldC(t0, nW2, Wp, bp);
        foldC(t0 + 2048, nW2, Wp, bp);
        arrive(&g_ctrC);
    }

    // ---------------- BN finalize on block 0 --------------------------------
    if (bid == 0) {
        waitFor(&g_ctrS, NSTATS);
        waitFor(&g_ctrC, NFOLD);
        int j = tid;
        float s0 = 0.f, s1 = 0.f, q0 = 0.f, q1 = 0.f;
        for (int b = 0; b < NSTATS; b += 2) {
            s0 += g_part[b * 512 + j];
            q0 += g_part[b * 512 + 256 + j];
            s1 += g_part[(b + 1) * 512 + j];
            q1 += g_part[(b + 1) * 512 + 256 + j];
        }
        float s = s0 + s1, q = q0 + q1;
        float mu = s * invE;
        float var = q * invE - mu * mu;
        float gg = gamma[j] * rsqrtf(var + 1e-5f);
        sh[j] = beta[j] - mu * gg;
#pragma unroll
        for (int d = 0; d < 8; d++) g_Mg[j * 8 + d] = gg * g_M[j * 8 + d];
        __syncthreads();
        int w = j >> 5, lane = j & 31;
        float acc = 0.f;
        for (int jj = lane; jj < 256; jj += 32) acc += sh[jj] * g_M[jj * 8 + w];
#pragma unroll
        for (int off = 16; off; off >>= 1)
            acc += __shfl_xor_sync(0xffffffffu, acc, off);
        if (lane == 0) g_const8[w] = acc + g_c3[w];
        arrive(&g_ctrR);
    }

    // ---------------- phase 2: output over this block's slice ---------------
    waitFor(&g_ctrR, 1);

    float* sWf = (float*)sW;
    float* sMf = (float*)sM;
    for (int i = tid; i < 2048; i += 256) {
        int j = i >> 3, d = i & 7;
        sWf[i] = W1[d * 256 + j];
        sMf[i] = g_Mg[i];
    }
    sB[tid] = b1[tid];
    if (tid < 8) sC[tid] = g_const8[tid];
    __syncthreads();

    int perO = (E + NBLK - 1) / NBLK;
    int startO = bid * perO;
    int endO = min(startO + perO, E);
    const float4* nf4 = (const float4*)nf;
    const float4* ea4 = (const float4*)ea;
    float4* out4 = (float4*)out;

    for (int e = startO + tid; e < endO; e += 256) {
        int a = ei[e], b = ei[E + e];
        float4 a0 = nf4[a * 2], a1 = nf4[a * 2 + 1];
        float4 b0 = nf4[b * 2], b1v = nf4[b * 2 + 1];
        float c[8];
        c[0] = 0.5f * (a0.x + b0.x); c[1] = 0.5f * (a0.y + b0.y);
        c[2] = 0.5f * (a0.z + b0.z); c[3] = 0.5f * (a0.w + b0.w);
        c[4] = 0.5f * (a1.x + b1v.x); c[5] = 0.5f * (a1.y + b1v.y);
        c[6] = 0.5f * (a1.z + b1v.z); c[7] = 0.5f * (a1.w + b1v.w);

        float y[8];
#pragma unroll
        for (int d = 0; d < 8; d++) y[d] = 0.f;

#pragma unroll 8
        for (int j = 0; j < 256; j++) {
            float4 w0 = sW[j * 2], w1 = sW[j * 2 + 1];
            float h = sB[j];
            h += c[0] * w0.x; h += c[1] * w0.y; h += c[2] * w0.z; h += c[3] * w0.w;
            h += c[4] * w1.x; h += c[5] * w1.y; h += c[6] * w1.z; h += c[7] * w1.w;
            h = fmaxf(h, 0.f);
            float4 m0 = sM[j * 2], m1 = sM[j * 2 + 1];
            y[0] += h * m0.x; y[1] += h * m0.y; y[2] += h * m0.z; y[3] += h * m0.w;
            y[4] += h * m1.x; y[5] += h * m1.y; y[6] += h * m1.z; y[7] += h * m1.w;
        }

        float4 e0 = ea4[e * 2], e1 = ea4[e * 2 + 1];
        float4 o0, o1;
        o0.x = e0.x + 0.5f * (y[0] + sC[0]);
        o0.y = e0.y + 0.5f * (y[1] + sC[1]);
        o0.z = e0.z + 0.5f * (y[2] + sC[2]);
        o0.w = e0.w + 0.5f * (y[3] + sC[3]);
        o1.x = e1.x + 0.5f * (y[4] + sC[4]);
        o1.y = e1.y + 0.5f * (y[5] + sC[5]);
        o1.z = e1.z + 0.5f * (y[6] + sC[6]);
        o1.w = e1.w + 0.5f * (y[7] + sC[7]);
        out4[e * 2] = o0;
        out4[e * 2 + 1] = o1;
    }
}

// ---------------------------------------------------------------------------
extern "C" void kernel_launch(void* const* d_in, const int* in_sizes, int n_in,
                              void* d_out, int out_size) {
    const float* edge_attr = (const float*)d_in[0];
    const float* nf        = (const float*)d_in[1];
    const int*   ei        = (const int*)d_in[2];
    // d_in[3..8]: edge-encoder params (dead code in reference)
    const float* nW1   = (const float*)d_in[9];
    const float* nb1   = (const float*)d_in[10];
    const float* ngam  = (const float*)d_in[11];
    const float* nbet  = (const float*)d_in[12];
    const float* nW2   = (const float*)d_in[13];
    const float* nb2   = (const float*)d_in[14];
    const float* Wv    = (const float*)d_in[15];
    const float* bv    = (const float*)d_in[16];
    const float* Wo    = (const float*)d_in[17];
    const float* bo    = (const float*)d_in[18];
    const float* Wp    = (const float*)d_in[19];
    const float* bp    = (const float*)d_in[20];
    float* out = (float*)d_out;

    int E = in_sizes[0] / 8;

    kReset<<<1, 32>>>();
    kFused<<<NBLK, 256>>>(nf, ei, nW1, nb1, ngam, nbet,
                          Wo, Wp, nb2, Wv, bv, bo, nW2, bp,
                          edge_attr, out, E, 1.0f / (float)E);
}

// round 15
// speedup vs baseline: 1.7515x; 1.0143x over previous
#include <cuda_runtime.h>

// ---------------------------------------------------------------------------
// CausalEdgeAttention — algebraically reduced, SINGLE fused persistent kernel.
//   out = edge_attr + 0.5*((relu(ctx@W1+b1) * g) @ M + const8)
//   ctx = 0.5*(nf[src]+nf[tgt]);  M = n_W2@Wv@Wo@Wp (256x8)
// R14: fusion confirmed (235us, ncu accounts for all time). Out phase is
//   FMA-pipe-bound (~17 fma/col scalar). Convert out inner loop to f32x2
//   (4 FMA2 dot seeded with bias + 4 FMA2 y-acc) -> ~40% fewer FMA cycles.
//   Stats/fold/fin phases frozen from R14.
// ---------------------------------------------------------------------------

#define NSTATS 584                 // blocks doing stats
#define NFOLD  8                   // blocks doing weight folding
#define NBLK   (NSTATS + NFOLD)    // 592 = 4/SM * 148 SMs, one wave
#define TILE   256

__device__ __align__(16) float g_U[256 * 8];
__device__ __align__(16) float g_V[256 * 8];
__device__ __align__(16) float g_M[256 * 8];
__device__ __align__(16) float g_Mg[256 * 8];
__device__ float g_c1[256];
__device__ float g_c2[256];
__device__ float g_c3[8];
__device__ __align__(16) float g_const8[8];
__device__ __align__(16) float g_part[NSTATS * 512];
__device__ int g_ctrA, g_ctrB, g_ctrC, g_ctrS, g_ctrR;

// ---- packed f32x2 helpers -------------------------------------------------
__device__ __forceinline__ unsigned long long pk2(float lo, float hi) {
    unsigned long long r;
    asm("mov.b64 %0, {%1, %2};" : "=l"(r) : "f"(lo), "f"(hi));
    return r;
}
__device__ __forceinline__ void upk2(unsigned long long v, float& lo, float& hi) {
    asm("mov.b64 {%0, %1}, %2;" : "=f"(lo), "=f"(hi) : "l"(v));
}
#define FMA2(d, a, b, c) asm("fma.rn.f32x2 %0, %1, %2, %3;" : "=l"(d) : "l"(a), "l"(b), "l"(c))
#define ADD2(d, a, b)    asm("add.rn.f32x2 %0, %1, %2;" : "=l"(d) : "l"(a), "l"(b))

#define HALF2C 0x3F0000003F000000ULL   // (0.5f, 0.5f)

// ---- spin barrier helpers -------------------------------------------------
__device__ __forceinline__ void arrive(int* ctr) {
    __syncthreads();
    __threadfence();
    if (threadIdx.x == 0) atomicAdd(ctr, 1);
}
__device__ __forceinline__ void waitFor(int* ctr, int target) {
    if (threadIdx.x == 0) {
        while (atomicAdd(ctr, 0) < target) __nanosleep(128);
        __threadfence();
    }
    __syncthreads();
}

// ---- reset kernel (counters must be zero at each graph replay) ------------
__global__ void kReset() {
    g_ctrA = 0; g_ctrB = 0; g_ctrC = 0; g_ctrS = 0; g_ctrR = 0;
}

// ---- fold stage bodies ----------------------------------------------------
__device__ void foldA(int t, const float* __restrict__ Wo,
                      const float* __restrict__ Wp, const float* __restrict__ nb2,
                      const float* __restrict__ Wv, const float* __restrict__ bv) {
    if (t < 2048) {
        int i = t >> 3, d = t & 7;
        float a0 = 0.f, a1 = 0.f, a2 = 0.f, a3 = 0.f;
        for (int k = 0; k < 256; k += 4) {
            a0 = fmaf(Wo[i * 256 + k],     Wp[k * 8 + d],       a0);
            a1 = fmaf(Wo[i * 256 + k + 1], Wp[(k + 1) * 8 + d], a1);
            a2 = fmaf(Wo[i * 256 + k + 2], Wp[(k + 2) * 8 + d], a2);
            a3 = fmaf(Wo[i * 256 + k + 3], Wp[(k + 3) * 8 + d], a3);
        }
        g_U[t] = (a0 + a1) + (a2 + a3);
    } else if (t < 2304) {
        int i = t - 2048;
        float a0 = bv[i], a1 = 0.f, a2 = 0.f, a3 = 0.f;
        for (int k = 0; k < 256; k += 4) {
            a0 = fmaf(nb2[k],     Wv[k * 256 + i],       a0);
            a1 = fmaf(nb2[k + 1], Wv[(k + 1) * 256 + i], a1);
            a2 = fmaf(nb2[k + 2], Wv[(k + 2) * 256 + i], a2);
            a3 = fmaf(nb2[k + 3], Wv[(k + 3) * 256 + i], a3);
        }
        g_c1[i] = (a0 + a1) + (a2 + a3);
    }
}

__device__ void foldB(int t, const float* __restrict__ Wv,
                      const float* __restrict__ Wo, const float* __restrict__ bo) {
    if (t < 2048) {
        int i = t >> 3, d = t & 7;
        float a0 = 0.f, a1 = 0.f, a2 = 0.f, a3 = 0.f;
        for (int k = 0; k < 256; k += 4) {
            a0 = fmaf(Wv[i * 256 + k],     g_U[k * 8 + d],       a0);
            a1 = fmaf(Wv[i * 256 + k + 1], g_U[(k + 1) * 8 + d], a1);
            a2 = fmaf(Wv[i * 256 + k + 2], g_U[(k + 2) * 8 + d], a2);
            a3 = fmaf(Wv[i * 256 + k + 3], g_U[(k + 3) * 8 + d], a3);
        }
        g_V[t] = (a0 + a1) + (a2 + a3);
    } else if (t < 2304) {
        int i = t - 2048;
        float a0 = bo[i], a1 = 0.f, a2 = 0.f, a3 = 0.f;
        for (int k = 0; k < 256; k += 4) {
            a0 = fmaf(g_c1[k],     Wo[k * 256 + i],       a0);
            a1 = fmaf(g_c1[k + 1], Wo[(k + 1) * 256 + i], a1);
            a2 = fmaf(g_c1[k + 2], Wo[(k + 2) * 256 + i], a2);
            a3 = fmaf(g_c1[k + 3], Wo[(k + 3) * 256 + i], a3);
        }
        g_c2[i] = (a0 + a1) + (a2 + a3);
    }
}

__device__ void foldC(int t, const float* __restrict__ nW2,
                      const float* __restrict__ Wp, const float* __restrict__ bp) {
    if (t < 2048) {
        int i = t >> 3, d = t & 7;
        float a0 = 0.f, a1 = 0.f, a2 = 0.f, a3 = 0.f;
        for (int k = 0; k < 256; k += 4) {
            a0 = fmaf(nW2[i * 256 + k],     g_V[k * 8 + d],       a0);
            a1 = fmaf(nW2[i * 256 + k + 1], g_V[(k + 1) * 8 + d], a1);
            a2 = fmaf(nW2[i * 256 + k + 2], g_V[(k + 2) * 8 + d], a2);
            a3 = fmaf(nW2[i * 256 + k + 3], g_V[(k + 3) * 8 + d], a3);
        }
        g_M[t] = (a0 + a1) + (a2 + a3);
    } else if (t < 2056) {
        int d = t - 2048;
        float acc = bp[d];
        for (int k = 0; k < 256; k++) acc = fmaf(g_c2[k], Wp[k * 8 + d], acc);
        g_c3[d] = acc;
    }
}

// ---- the fused kernel -----------------------------------------------------
__global__ void __launch_bounds__(256, 4) kFused(
    const float* __restrict__ nf, const int* __restrict__ ei,
    const float* __restrict__ W1, const float* __restrict__ b1,
    const float* __restrict__ gamma, const float* __restrict__ beta,
    const float* __restrict__ Wo, const float* __restrict__ Wp,
    const float* __restrict__ nb2, const float* __restrict__ Wv,
    const float* __restrict__ bv, const float* __restrict__ bo,
    const float* __restrict__ nW2, const float* __restrict__ bp,
    const float* __restrict__ ea, float* __restrict__ out,
    int E, float invE) {
    __shared__ unsigned long long sCtx[2][TILE][4];   // 16KB (stats phase)
    __shared__ ulonglong2 sWp[256];                   // 4KB  (out: w01,w23 *0.5)
    __shared__ ulonglong2 sWq[256];                   // 4KB  (out: w45,w67 *0.5)
    __shared__ ulonglong2 sMp[256];                   // 4KB  (out: m01,m23)
    __shared__ ulonglong2 sMq[256];                   // 4KB  (out: m45,m67)
    __shared__ unsigned long long sB2[256];           // 2KB  (b1[j],0)
    __shared__ unsigned long long sC2[4];             // packed const8
    __shared__ float sh[256];                         // fin phase (block 0)

    int tid = threadIdx.x;
    int bid = blockIdx.x;
    const ulonglong4* nfq = (const ulonglong4*)nf;

    if (bid < NSTATS) {
        // ---------------- phase 1: BN stats over this block's edge slice ----
        int j = tid;
        unsigned long long w01 = pk2(0.5f * W1[0 * 256 + j], 0.5f * W1[1 * 256 + j]);
        unsigned long long w23 = pk2(0.5f * W1[2 * 256 + j], 0.5f * W1[3 * 256 + j]);
        unsigned long long w45 = pk2(0.5f * W1[4 * 256 + j], 0.5f * W1[5 * 256 + j]);
        unsigned long long w67 = pk2(0.5f * W1[6 * 256 + j], 0.5f * W1[7 * 256 + j]);
        unsigned long long b2 = pk2(b1[j], 0.f);

        float s = 0.f, q = 0.f;
        int per = (E + NSTATS - 1) / NSTATS;
        int start = bid * per;
        int len = min(per, E - start);
        if (len < 0) len = 0;
        int nt = (len + TILE - 1) / TILE;

        if (tid < len) {
            int e = start + tid;
            int a = ei[e], b = ei[E + e];
            ulonglong4 A = nfq[a], B = nfq[b];
            unsigned long long c0, c1, c2, c3;
            ADD2(c0, A.x, B.x); ADD2(c1, A.y, B.y);
            ADD2(c2, A.z, B.z); ADD2(c3, A.w, B.w);
            sCtx[0][tid][0] = c0; sCtx[0][tid][1] = c1;
            sCtx[0][tid][2] = c2; sCtx[0][tid][3] = c3;
        }

        for (int t = 0; t < nt; t++) {
            __syncthreads();
            if (t + 1 < nt) {
                int e = start + (t + 1) * TILE + tid;
                if (e < start + len) {
                    int buf = (t + 1) & 1;
                    int a = ei[e], b = ei[E + e];
                    ulonglong4 A = nfq[a], B = nfq[b];
                    unsigned long long c0, c1, c2, c3;
                    ADD2(c0, A.x, B.x); ADD2(c1, A.y, B.y);
                    ADD2(c2, A.z, B.z); ADD2(c3, A.w, B.w);
                    sCtx[buf][tid][0] = c0; sCtx[buf][tid][1] = c1;
                    sCtx[buf][tid][2] = c2; sCtx[buf][tid][3] = c3;
                }
            }
            int buf = t & 1;
            int tlen = min(TILE, len - t * TILE);
            const ulonglong2* cb = (const ulonglong2*)&sCtx[buf][0][0];
#pragma unroll 4
            for (int tt = 0; tt < tlen; tt++) {
                ulonglong2 c01 = cb[2 * tt];
                ulonglong2 c23 = cb[2 * tt + 1];
                unsigned long long acc;
                FMA2(acc, c01.x, w01, b2);
                FMA2(acc, c01.y, w23, acc);
                FMA2(acc, c23.x, w45, acc);
                FMA2(acc, c23.y, w67, acc);
                float lo, hi;
                upk2(acc, lo, hi);
                float h = fmaxf(lo + hi, 0.f);
                s += h;
                q = fmaf(h, h, q);
            }
        }
        g_part[bid * 512 + tid] = s;
        g_part[bid * 512 + 256 + tid] = q;
        arrive(&g_ctrS);
    } else {
        // ---------------- fold chain on 8 blocks (concurrent with stats) ----
        int t0 = (bid - NSTATS) * 256 + tid;
        foldA(t0, Wo, Wp, nb2, Wv, bv);
        foldA(t0 + 2048, Wo, Wp, nb2, Wv, bv);
        arrive(&g_ctrA);
        waitFor(&g_ctrA, NFOLD);
        foldB(t0, Wv, Wo, bo);
        foldB(t0 + 2048, Wv, Wo, bo);
        arrive(&g_ctrB);
        waitFor(&g_ctrB, NFOLD);
        foldC(t0, nW2, Wp, bp);
        foldC(t0 + 2048, nW2, Wp, bp);
        arrive(&g_ctrC);
    }

    // ---------------- BN finalize on block 0 --------------------------------
    if (bid == 0) {
        waitFor(&g_ctrS, NSTATS);
        waitFor(&g_ctrC, NFOLD);
        int j = tid;
        float s0 = 0.f, s1 = 0.f, q0 = 0.f, q1 = 0.f;
        for (int b = 0; b < NSTATS; b += 2) {
            s0 += g_part[b * 512 + j];
            q0 += g_part[b * 512 + 256 + j];
            s1 += g_part[(b + 1) * 512 + j];
            q1 += g_part[(b + 1) * 512 + 256 + j];
        }
        float s = s0 + s1, q = q0 + q1;
        float mu = s * invE;
        float var = q * invE - mu * mu;
        float gg = gamma[j] * rsqrtf(var + 1e-5f);
        sh[j] = beta[j] - mu * gg;
#pragma unroll
        for (int d = 0; d < 8; d++) g_Mg[j * 8 + d] = gg * g_M[j * 8 + d];
        __syncthreads();
        int w = j >> 5, lane = j & 31;
        float acc = 0.f;
        for (int jj = lane; jj < 256; jj += 32) acc += sh[jj] * g_M[jj * 8 + w];
#pragma unroll
        for (int off = 16; off; off >>= 1)
            acc += __shfl_xor_sync(0xffffffffu, acc, off);
        if (lane == 0) g_const8[w] = acc + g_c3[w];
        arrive(&g_ctrR);
    }

    // ---------------- phase 2: output over this block's slice ---------------
    waitFor(&g_ctrR, 1);

    {
        int j = tid;   // one column per thread (256 threads)
        ulonglong2 wv1, wv2;
        wv1.x = pk2(0.5f * W1[0 * 256 + j], 0.5f * W1[1 * 256 + j]);
        wv1.y = pk2(0.5f * W1[2 * 256 + j], 0.5f * W1[3 * 256 + j]);
        wv2.x = pk2(0.5f * W1[4 * 256 + j], 0.5f * W1[5 * 256 + j]);
        wv2.y = pk2(0.5f * W1[6 * 256 + j], 0.5f * W1[7 * 256 + j]);
        sWp[j] = wv1;
        sWq[j] = wv2;
        sMp[j] = ((const ulonglong2*)g_Mg)[2 * j];
        sMq[j] = ((const ulonglong2*)g_Mg)[2 * j + 1];
        sB2[j] = pk2(b1[j], 0.f);
        if (tid < 4) sC2[tid] = ((const unsigned long long*)g_const8)[tid];
    }
    __syncthreads();

    int perO = (E + NBLK - 1) / NBLK;
    int startO = bid * perO;
    int endO = min(startO + perO, E);
    const ulonglong4* eaq = (const ulonglong4*)ea;
    ulonglong4* outq = (ulonglong4*)out;
    const unsigned long long H2 = HALF2C;

    for (int e = startO + tid; e < endO; e += 256) {
        int a = ei[e], b = ei[E + e];
        ulonglong4 A = nfq[a], B = nfq[b];
        unsigned long long c0, c1, c2, c3;
        ADD2(c0, A.x, B.x); ADD2(c1, A.y, B.y);
        ADD2(c2, A.z, B.z); ADD2(c3, A.w, B.w);

        unsigned long long y0 = 0ull, y1 = 0ull, y2 = 0ull, y3 = 0ull;

#pragma unroll 8
        for (int j = 0; j < 256; j++) {
            ulonglong2 wA = sWp[j];
            ulonglong2 wB = sWq[j];
            unsigned long long t;
            FMA2(t, c0, wA.x, sB2[j]);
            FMA2(t, c1, wA.y, t);
            FMA2(t, c2, wB.x, t);
            FMA2(t, c3, wB.y, t);
            float lo, hi;
            upk2(t, lo, hi);
            float h = fmaxf(lo + hi, 0.f);
            unsigned long long h2 = pk2(h, h);
            ulonglong2 m0 = sMp[j];
            ulonglong2 m1 = sMq[j];
            FMA2(y0, h2, m0.x, y0);
            FMA2(y1, h2, m0.y, y1);
            FMA2(y2, h2, m1.x, y2);
            FMA2(y3, h2, m1.y, y3);
        }

        ulonglong4 ev = eaq[e];
        ulonglong4 ov;
        unsigned long long t;
        ADD2(t, y0, sC2[0]); FMA2(ov.x, t, H2, ev.x);
        ADD2(t, y1, sC2[1]); FMA2(ov.y, t, H2, ev.y);
        ADD2(t, y2, sC2[2]); FMA2(ov.z, t, H2, ev.z);
        ADD2(t, y3, sC2[3]); FMA2(ov.w, t, H2, ev.w);
        outq[e] = ov;
    }
}

// ---------------------------------------------------------------------------
extern "C" void kernel_launch(void* const* d_in, const int* in_sizes, int n_in,
                              void* d_out, int out_size) {
    const float* edge_attr = (const float*)d_in[0];
    const float* nf        = (const float*)d_in[1];
    const int*   ei        = (const int*)d_in[2];
    // d_in[3..8]: edge-encoder params (dead code in reference)
    const float* nW1   = (const float*)d_in[9];
    const float* nb1   = (const float*)d_in[10];
    const float* ngam  = (const float*)d_in[11];
    const float* nbet  = (const float*)d_in[12];
    const float* nW2   = (const float*)d_in[13];
    const float* nb2   = (const float*)d_in[14];
    const float* Wv    = (const float*)d_in[15];
    const float* bv    = (const float*)d_in[16];
    const float* Wo    = (const float*)d_in[17];
    const float* bo    = (const float*)d_in[18];
    const float* Wp    = (const float*)d_in[19];
    const float* bp    = (const float*)d_in[20];
    float* out = (float*)d_out;

    int E = in_sizes[0] / 8;

    kReset<<<1, 32>>>();
    kFused<<<NBLK, 256>>>(nf, ei, nW1, nb1, ngam, nbet,
                          Wo, Wp, nb2, Wv, bv, bo, nW2, bp,
                          edge_attr, out, E, 1.0f / (float)E);
}